// round 7
// baseline (speedup 1.0000x reference)
#include <cuda_runtime.h>

// MultiLayerGRU fused: 3 stacked GRU layers, T=1024, B=4096, I=5, H0=15, H1=10, H2=2.
// One warp per SIX batch elements: three independent f32x2 packed batch-pairs
// per lane (weights shared across pairs -> 3rd pair costs only accumulators).
// 683 working warps in 114 blocks x 192 thr: exactly one block per SM, no
// wave imbalance. Lane roles:
//   lanes  0..14 : layer-0 units
//   lanes 15..24 : layer-1 units
//   lanes 25..26 : layer-2 units (write the output)
//   lanes 27..31 : x-feature loaders (prefetch x[t] into registers)
// Wavefront over layers: iteration s computes h0(s), h1(s-1), h2(s-2).
// shfl source: src_k = (base + k) mod 32, base in {27,0,15} (shfl wraps srcLane).
// Batch tail: 4096 = 682*6 + 4; out-of-range pairs are clamped for loads and
// store-suppressed (whole pairs only: b0 even, BATCH even).

#define T_STEPS 1024
#define BATCH   4096
#define IN_DIM  5

using u64 = unsigned long long;

__device__ __forceinline__ u64 pack2(float a, float b) {
    u64 r;
    asm("mov.b64 %0, {%1, %2};" : "=l"(r) : "f"(a), "f"(b));
    return r;
}
__device__ __forceinline__ void unpack2(u64 p, float& a, float& b) {
    asm("mov.b64 {%0, %1}, %2;" : "=f"(a), "=f"(b) : "l"(p));
}
__device__ __forceinline__ u64 fma2(u64 a, u64 b, u64 c) {
    u64 d;
    asm("fma.rn.f32x2 %0, %1, %2, %3;" : "=l"(d) : "l"(a), "l"(b), "l"(c));
    return d;
}

__device__ __forceinline__ float fsig(float a) {
    return __fdividef(1.0f, 1.0f + __expf(-a));
}
__device__ __forceinline__ float ftanh_(float v) {
    return 1.0f - 2.0f * __fdividef(1.0f, 1.0f + __expf(2.0f * v));
}

__global__ __launch_bounds__(192)
void gru3_fused_kernel(
    const float* __restrict__ x,
    const float* __restrict__ w_ih0, const float* __restrict__ w_hh0,
    const float* __restrict__ b_ih0, const float* __restrict__ b_hh0,
    const float* __restrict__ w_ih1, const float* __restrict__ w_hh1,
    const float* __restrict__ b_ih1, const float* __restrict__ b_hh1,
    const float* __restrict__ w_ih2, const float* __restrict__ w_hh2,
    const float* __restrict__ b_ih2, const float* __restrict__ b_hh2,
    float* __restrict__ out)
{
    // ---- stage all weights into shared once ----
    __shared__ float sw[1884];
    {
        int t = threadIdx.x;
        for (int i = t; i < 225; i += 192) sw[i]        = w_ih0[i];
        for (int i = t; i < 675; i += 192) sw[225 + i]  = w_hh0[i];
        for (int i = t; i <  45; i += 192) sw[900 + i]  = b_ih0[i];
        for (int i = t; i <  45; i += 192) sw[945 + i]  = b_hh0[i];
        for (int i = t; i < 450; i += 192) sw[990 + i]  = w_ih1[i];
        for (int i = t; i < 300; i += 192) sw[1440 + i] = w_hh1[i];
        for (int i = t; i <  30; i += 192) sw[1740 + i] = b_ih1[i];
        for (int i = t; i <  30; i += 192) sw[1770 + i] = b_hh1[i];
        for (int i = t; i <  60; i += 192) sw[1800 + i] = w_ih2[i];
        for (int i = t; i <  12; i += 192) sw[1860 + i] = w_hh2[i];
        for (int i = t; i <   6; i += 192) sw[1872 + i] = b_ih2[i];
        for (int i = t; i <   6; i += 192) sw[1878 + i] = b_hh2[i];
    }
    __syncthreads();
    const float* s_wih0 = sw;
    const float* s_whh0 = sw + 225;
    const float* s_bih0 = sw + 900;
    const float* s_bhh0 = sw + 945;
    const float* s_wih1 = sw + 990;
    const float* s_whh1 = sw + 1440;
    const float* s_bih1 = sw + 1740;
    const float* s_bhh1 = sw + 1770;
    const float* s_wih2 = sw + 1800;
    const float* s_whh2 = sw + 1860;
    const float* s_bih2 = sw + 1872;
    const float* s_bhh2 = sw + 1878;

    const int lane = threadIdx.x & 31;
    const int gw   = blockIdx.x * 6 + (threadIdx.x >> 5);
    const int b0   = gw * 6;             // batches b0 .. b0+5 (may exceed BATCH)

    // ---- per-lane register-resident weights (unified k-loop, k = 0..24) ----
    float wr[25], wz[25], wni[15], wnh[20];
#pragma unroll
    for (int k = 0; k < 25; k++) { wr[k] = 0.f; wz[k] = 0.f; }
#pragma unroll
    for (int k = 0; k < 15; k++) wni[k] = 0.f;
#pragma unroll
    for (int k = 0; k < 20; k++) wnh[k] = 0.f;
    float br = 0.f, bz = 0.f, bni = 0.f, bnh = 0.f;

    if (lane < 15) {
        const int u = lane;
#pragma unroll
        for (int k = 0; k < 5; k++) {
            wr[k]  = s_wih0[u * 5 + k];
            wz[k]  = s_wih0[(15 + u) * 5 + k];
            wni[k] = s_wih0[(30 + u) * 5 + k];
        }
#pragma unroll
        for (int j = 0; j < 15; j++) {
            wr[5 + j]  = s_whh0[u * 15 + j];
            wz[5 + j]  = s_whh0[(15 + u) * 15 + j];
            wnh[j]     = s_whh0[(30 + u) * 15 + j];
        }
        br  = s_bih0[u] + s_bhh0[u];
        bz  = s_bih0[15 + u] + s_bhh0[15 + u];
        bni = s_bih0[30 + u];
        bnh = s_bhh0[30 + u];
    } else if (lane < 25) {
        const int u = lane - 15;
#pragma unroll
        for (int k = 0; k < 15; k++) {
            wr[k]  = s_wih1[u * 15 + k];
            wz[k]  = s_wih1[(10 + u) * 15 + k];
            wni[k] = s_wih1[(20 + u) * 15 + k];
        }
#pragma unroll
        for (int j = 0; j < 10; j++) {
            wr[15 + j]  = s_whh1[u * 10 + j];
            wz[15 + j]  = s_whh1[(10 + u) * 10 + j];
            wnh[10 + j] = s_whh1[(20 + u) * 10 + j];
        }
        br  = s_bih1[u] + s_bhh1[u];
        bz  = s_bih1[10 + u] + s_bhh1[10 + u];
        bni = s_bih1[20 + u];
        bnh = s_bhh1[20 + u];
    } else if (lane < 27) {
        const int u = lane - 25;
#pragma unroll
        for (int k = 0; k < 10; k++) {
            wr[k]  = s_wih2[u * 10 + k];
            wz[k]  = s_wih2[(2 + u) * 10 + k];
            wni[k] = s_wih2[(4 + u) * 10 + k];
        }
#pragma unroll
        for (int j = 0; j < 2; j++) {
            wr[10 + j] = s_whh2[u * 2 + j];
            wz[10 + j] = s_whh2[(2 + u) * 2 + j];
            wnh[5 + j] = s_whh2[(4 + u) * 2 + j];
        }
        br  = s_bih2[u] + s_bhh2[u];
        bz  = s_bih2[2 + u] + s_bhh2[2 + u];
        bni = s_bih2[4 + u];
        bnh = s_bhh2[4 + u];
    }

    // duplicate-packed weights (w,w) for f32x2 FMA — shared by all 3 pairs
    u64 wr2[25], wz2[25], wni2[15], wnh2[20];
#pragma unroll
    for (int k = 0; k < 25; k++) { wr2[k] = pack2(wr[k], wr[k]); wz2[k] = pack2(wz[k], wz[k]); }
#pragma unroll
    for (int k = 0; k < 15; k++) wni2[k] = pack2(wni[k], wni[k]);
#pragma unroll
    for (int k = 0; k < 20; k++) wnh2[k] = pack2(wnh[k], wnh[k]);
    const u64 br2  = pack2(br, br);
    const u64 bz2  = pack2(bz, bz);
    const u64 bni2 = pack2(bni, bni);
    const u64 bnh2 = pack2(bnh, bnh);

    // shfl base per lane class: src_k = base + k (shfl wraps mod 32)
    const int base = (lane < 15) ? 27 : (lane < 25) ? 0 : 15;

    const bool isLoader = (lane >= 27);
    const bool isOut    = (lane == 25) || (lane == 26);
    // wavefront delay per lane; loader lanes never commit
    const int d = (lane < 15) ? 0 : (lane < 25) ? 1 : (lane < 27) ? 2 : 0x40000000;

    // per-pair clamped bases + store guards (tail handling; whole pairs only)
    const int feat = isLoader ? (lane - 27) : 0;
    const int u2   = (lane >= 25) ? (lane - 25) : 0;
    const float* xpr[3];
    float* opr[3];
    bool gOK[3];
#pragma unroll
    for (int j = 0; j < 3; j++) {
        int bp = b0 + 2 * j;
        gOK[j] = (bp < BATCH);
        if (bp > BATCH - 2) bp = BATCH - 2;       // clamp (loads stay in-bounds)
        xpr[j] = x + (size_t)bp * IN_DIM + feat;
        opr[j] = out + (size_t)bp * 2 + u2;
    }

    float h[6]  = {0.f, 0.f, 0.f, 0.f, 0.f, 0.f};  // hidden state, 6 batches
    float xn[6] = {0.f, 0.f, 0.f, 0.f, 0.f, 0.f};  // prefetched x(t+1)
    u64 sh[3] = {0, 0, 0};                          // packed operands per pair
    if (isLoader) {
#pragma unroll
        for (int j = 0; j < 3; j++) {
            sh[j]       = pack2(xpr[j][0], xpr[j][IN_DIM]);          // x(0)
            xn[2*j]     = xpr[j][BATCH * IN_DIM];                    // x(1)
            xn[2*j + 1] = xpr[j][BATCH * IN_DIM + IN_DIM];
        }
    }

    for (int s = 0; s < T_STEPS + 2; ++s) {
        u64 ar[3], az[3], ani[3], anh[3];
#pragma unroll
        for (int j = 0; j < 3; j++) { ar[j] = br2; az[j] = bz2; ani[j] = bni2; anh[j] = bnh2; }
#pragma unroll
        for (int k = 0; k < 25; k++) {
            u64 v0 = __shfl_sync(0xffffffffu, sh[0], base + k);      // wraps mod 32
            u64 v1 = __shfl_sync(0xffffffffu, sh[1], base + k);
            u64 v2 = __shfl_sync(0xffffffffu, sh[2], base + k);
            ar[0] = fma2(wr2[k], v0, ar[0]);
            ar[1] = fma2(wr2[k], v1, ar[1]);
            ar[2] = fma2(wr2[k], v2, ar[2]);
            az[0] = fma2(wz2[k], v0, az[0]);
            az[1] = fma2(wz2[k], v1, az[1]);
            az[2] = fma2(wz2[k], v2, az[2]);
            if (k < 15) {
                ani[0] = fma2(wni2[k], v0, ani[0]);
                ani[1] = fma2(wni2[k], v1, ani[1]);
                ani[2] = fma2(wni2[k], v2, ani[2]);
            }
            if (k >= 5) {
                anh[0] = fma2(wnh2[k - 5], v0, anh[0]);
                anh[1] = fma2(wnh2[k - 5], v1, anh[1]);
                anh[2] = fma2(wnh2[k - 5], v2, anh[2]);
            }
        }

        float hn[6];
#pragma unroll
        for (int j = 0; j < 3; j++) {
            float arA, arB, azA, azB, aniA, aniB, anhA, anhB;
            unpack2(ar[j], arA, arB);
            unpack2(az[j], azA, azB);
            unpack2(ani[j], aniA, aniB);
            unpack2(anh[j], anhA, anhB);
            float rA = fsig(arA), rB = fsig(arB);
            float zA = fsig(azA), zB = fsig(azB);
            float nA = ftanh_(fmaf(rA, anhA, aniA));
            float nB = ftanh_(fmaf(rB, anhB, aniB));
            hn[2*j]     = fmaf(zA, h[2*j] - nA, nA);       // (1-z)*n + z*h
            hn[2*j + 1] = fmaf(zB, h[2*j + 1] - nB, nB);
        }

        bool valid = (s >= d) && (s < T_STEPS + d);
        if (valid) {
#pragma unroll
            for (int i = 0; i < 6; i++) h[i] = hn[i];
        }
        if (valid && isOut) {
            size_t o = (size_t)(s - 2) * (BATCH * 2);
#pragma unroll
            for (int j = 0; j < 3; j++) {
                if (gOK[j]) {
                    opr[j][o]     = hn[2*j];
                    opr[j][o + 2] = hn[2*j + 1];
                }
            }
        }

        if (isLoader) {
#pragma unroll
            for (int j = 0; j < 3; j++) sh[j] = pack2(xn[2*j], xn[2*j + 1]);  // x(s+1)
            int t2 = s + 2;
            bool inb = (t2 < T_STEPS);
            size_t xo = (size_t)t2 * (BATCH * IN_DIM);
#pragma unroll
            for (int j = 0; j < 3; j++) {
                xn[2*j]     = inb ? xpr[j][xo] : 0.f;
                xn[2*j + 1] = inb ? xpr[j][xo + IN_DIM] : 0.f;
            }
        } else {
#pragma unroll
            for (int j = 0; j < 3; j++) sh[j] = pack2(h[2*j], h[2*j + 1]);
        }
    }
}

extern "C" void kernel_launch(void* const* d_in, const int* in_sizes, int n_in,
                              void* d_out, int out_size)
{
    (void)in_sizes; (void)n_in; (void)out_size;
    const float* x     = (const float*)d_in[0];
    const float* w_ih0 = (const float*)d_in[1];
    const float* w_hh0 = (const float*)d_in[2];
    const float* b_ih0 = (const float*)d_in[3];
    const float* b_hh0 = (const float*)d_in[4];
    const float* w_ih1 = (const float*)d_in[5];
    const float* w_hh1 = (const float*)d_in[6];
    const float* b_ih1 = (const float*)d_in[7];
    const float* b_hh1 = (const float*)d_in[8];
    const float* w_ih2 = (const float*)d_in[9];
    const float* w_hh2 = (const float*)d_in[10];
    const float* b_ih2 = (const float*)d_in[11];
    const float* b_hh2 = (const float*)d_in[12];

    // 6 batches per warp: ceil(4096/6)=683 warps -> 114 blocks x 6 warps.
    // 114 blocks <= 148 SMs: exactly one block per SM, no wave imbalance.
    gru3_fused_kernel<<<114, 192>>>(
        x, w_ih0, w_hh0, b_ih0, b_hh0,
        w_ih1, w_hh1, b_ih1, b_hh1,
        w_ih2, w_hh2, b_ih2, b_hh2,
        (float*)d_out);
}

// round 8
// speedup vs baseline: 1.5489x; 1.5489x over previous
#include <cuda_runtime.h>

// MultiLayerGRU fused: 3 stacked GRU layers, T=1024, B=4096, I=5, H0=15, H1=10, H2=2.
// One warp per SIX batch elements: three independent f32x2 packed batch-pairs
// per lane; weights shared across pairs (pair #3 costs only accumulators).
// __launch_bounds__(160,1) is load-bearing: without min-blocks=1 ptxas targets
// occupancy 2, caps regs at ~170 and spills the weight arrays (R7 failure).
// Geometry: 137 blocks x 160 thr (5 warps) = 685 warps >= ceil(4096/6);
// one block per SM, 30 batches per SM, equal load.
// Lane roles:
//   lanes  0..14 : layer-0 units
//   lanes 15..24 : layer-1 units
//   lanes 25..26 : layer-2 units (write the output)
//   lanes 27..31 : x-feature loaders (prefetch x[t] into registers)
// Wavefront over layers: iteration s computes h0(s), h1(s-1), h2(s-2).
// shfl source: src_k = (base + k) mod 32, base in {27,0,15}.
// Batch tail: base batch clamped to BATCH-6; overlapping warps recompute the
// same batches and store identical values (deterministic, benign).

#define T_STEPS 1024
#define BATCH   4096
#define IN_DIM  5

using u64 = unsigned long long;

__device__ __forceinline__ u64 pack2(float a, float b) {
    u64 r;
    asm("mov.b64 %0, {%1, %2};" : "=l"(r) : "f"(a), "f"(b));
    return r;
}
__device__ __forceinline__ void unpack2(u64 p, float& a, float& b) {
    asm("mov.b64 {%0, %1}, %2;" : "=f"(a), "=f"(b) : "l"(p));
}
__device__ __forceinline__ u64 fma2(u64 a, u64 b, u64 c) {
    u64 d;
    asm("fma.rn.f32x2 %0, %1, %2, %3;" : "=l"(d) : "l"(a), "l"(b), "l"(c));
    return d;
}

__device__ __forceinline__ float fsig(float a) {
    return __fdividef(1.0f, 1.0f + __expf(-a));
}
__device__ __forceinline__ float ftanh_(float v) {
    return 1.0f - 2.0f * __fdividef(1.0f, 1.0f + __expf(2.0f * v));
}

__global__ __launch_bounds__(160, 1)
void gru3_fused_kernel(
    const float* __restrict__ x,
    const float* __restrict__ w_ih0, const float* __restrict__ w_hh0,
    const float* __restrict__ b_ih0, const float* __restrict__ b_hh0,
    const float* __restrict__ w_ih1, const float* __restrict__ w_hh1,
    const float* __restrict__ b_ih1, const float* __restrict__ b_hh1,
    const float* __restrict__ w_ih2, const float* __restrict__ w_hh2,
    const float* __restrict__ b_ih2, const float* __restrict__ b_hh2,
    float* __restrict__ out)
{
    // ---- stage all weights into shared once ----
    __shared__ float sw[1884];
    {
        int t = threadIdx.x;
        for (int i = t; i < 225; i += 160) sw[i]        = w_ih0[i];
        for (int i = t; i < 675; i += 160) sw[225 + i]  = w_hh0[i];
        for (int i = t; i <  45; i += 160) sw[900 + i]  = b_ih0[i];
        for (int i = t; i <  45; i += 160) sw[945 + i]  = b_hh0[i];
        for (int i = t; i < 450; i += 160) sw[990 + i]  = w_ih1[i];
        for (int i = t; i < 300; i += 160) sw[1440 + i] = w_hh1[i];
        for (int i = t; i <  30; i += 160) sw[1740 + i] = b_ih1[i];
        for (int i = t; i <  30; i += 160) sw[1770 + i] = b_hh1[i];
        for (int i = t; i <  60; i += 160) sw[1800 + i] = w_ih2[i];
        for (int i = t; i <  12; i += 160) sw[1860 + i] = w_hh2[i];
        for (int i = t; i <   6; i += 160) sw[1872 + i] = b_ih2[i];
        for (int i = t; i <   6; i += 160) sw[1878 + i] = b_hh2[i];
    }
    __syncthreads();
    const float* s_wih0 = sw;
    const float* s_whh0 = sw + 225;
    const float* s_bih0 = sw + 900;
    const float* s_bhh0 = sw + 945;
    const float* s_wih1 = sw + 990;
    const float* s_whh1 = sw + 1440;
    const float* s_bih1 = sw + 1740;
    const float* s_bhh1 = sw + 1770;
    const float* s_wih2 = sw + 1800;
    const float* s_whh2 = sw + 1860;
    const float* s_bih2 = sw + 1872;
    const float* s_bhh2 = sw + 1878;

    const int lane = threadIdx.x & 31;
    const int gw   = blockIdx.x * 5 + (threadIdx.x >> 5);
    int bc = gw * 6;                          // base batch, clamped for tail
    if (bc > BATCH - 6) bc = BATCH - 6;       // redundant recompute, same values

    // ---- per-lane register-resident weights (unified k-loop, k = 0..24) ----
    float wr[25], wz[25], wni[15], wnh[20];
#pragma unroll
    for (int k = 0; k < 25; k++) { wr[k] = 0.f; wz[k] = 0.f; }
#pragma unroll
    for (int k = 0; k < 15; k++) wni[k] = 0.f;
#pragma unroll
    for (int k = 0; k < 20; k++) wnh[k] = 0.f;
    float br = 0.f, bz = 0.f, bni = 0.f, bnh = 0.f;

    if (lane < 15) {
        const int u = lane;
#pragma unroll
        for (int k = 0; k < 5; k++) {
            wr[k]  = s_wih0[u * 5 + k];
            wz[k]  = s_wih0[(15 + u) * 5 + k];
            wni[k] = s_wih0[(30 + u) * 5 + k];
        }
#pragma unroll
        for (int j = 0; j < 15; j++) {
            wr[5 + j]  = s_whh0[u * 15 + j];
            wz[5 + j]  = s_whh0[(15 + u) * 15 + j];
            wnh[j]     = s_whh0[(30 + u) * 15 + j];
        }
        br  = s_bih0[u] + s_bhh0[u];
        bz  = s_bih0[15 + u] + s_bhh0[15 + u];
        bni = s_bih0[30 + u];
        bnh = s_bhh0[30 + u];
    } else if (lane < 25) {
        const int u = lane - 15;
#pragma unroll
        for (int k = 0; k < 15; k++) {
            wr[k]  = s_wih1[u * 15 + k];
            wz[k]  = s_wih1[(10 + u) * 15 + k];
            wni[k] = s_wih1[(20 + u) * 15 + k];
        }
#pragma unroll
        for (int j = 0; j < 10; j++) {
            wr[15 + j]  = s_whh1[u * 10 + j];
            wz[15 + j]  = s_whh1[(10 + u) * 10 + j];
            wnh[10 + j] = s_whh1[(20 + u) * 10 + j];
        }
        br  = s_bih1[u] + s_bhh1[u];
        bz  = s_bih1[10 + u] + s_bhh1[10 + u];
        bni = s_bih1[20 + u];
        bnh = s_bhh1[20 + u];
    } else if (lane < 27) {
        const int u = lane - 25;
#pragma unroll
        for (int k = 0; k < 10; k++) {
            wr[k]  = s_wih2[u * 10 + k];
            wz[k]  = s_wih2[(2 + u) * 10 + k];
            wni[k] = s_wih2[(4 + u) * 10 + k];
        }
#pragma unroll
        for (int j = 0; j < 2; j++) {
            wr[10 + j] = s_whh2[u * 2 + j];
            wz[10 + j] = s_whh2[(2 + u) * 2 + j];
            wnh[5 + j] = s_whh2[(4 + u) * 2 + j];
        }
        br  = s_bih2[u] + s_bhh2[u];
        bz  = s_bih2[2 + u] + s_bhh2[2 + u];
        bni = s_bih2[4 + u];
        bnh = s_bhh2[4 + u];
    }

    // duplicate-packed weights (w,w) for f32x2 FMA — shared by all 3 pairs
    u64 wr2[25], wz2[25], wni2[15], wnh2[20];
#pragma unroll
    for (int k = 0; k < 25; k++) { wr2[k] = pack2(wr[k], wr[k]); wz2[k] = pack2(wz[k], wz[k]); }
#pragma unroll
    for (int k = 0; k < 15; k++) wni2[k] = pack2(wni[k], wni[k]);
#pragma unroll
    for (int k = 0; k < 20; k++) wnh2[k] = pack2(wnh[k], wnh[k]);
    const u64 br2  = pack2(br, br);
    const u64 bz2  = pack2(bz, bz);
    const u64 bni2 = pack2(bni, bni);
    const u64 bnh2 = pack2(bnh, bnh);

    // shfl base per lane class: src_k = base + k (shfl wraps mod 32)
    const int base = (lane < 15) ? 27 : (lane < 25) ? 0 : 15;

    const bool isLoader = (lane >= 27);
    const bool isOut    = (lane == 25) || (lane == 26);
    // wavefront delay per lane; loader lanes never commit
    const int d = (lane < 15) ? 0 : (lane < 25) ? 1 : (lane < 27) ? 2 : 0x40000000;

    // single base pointers; batch pairs at immediate offsets (j*2*IN_DIM / j*4)
    const int feat = isLoader ? (lane - 27) : 0;
    const float* xp = x + (size_t)bc * IN_DIM + feat;
    const int u2 = (lane >= 25) ? (lane - 25) : 0;
    float* op = out + (size_t)bc * 2 + u2;

    float h[6]  = {0.f, 0.f, 0.f, 0.f, 0.f, 0.f};  // hidden state, 6 batches
    float xn[6] = {0.f, 0.f, 0.f, 0.f, 0.f, 0.f};  // prefetched x(t+1)
    u64 sh[3] = {0, 0, 0};                          // packed operands per pair
    if (isLoader) {
#pragma unroll
        for (int j = 0; j < 3; j++) {
            sh[j]       = pack2(xp[j * 2 * IN_DIM], xp[j * 2 * IN_DIM + IN_DIM]);    // x(0)
            xn[2*j]     = xp[BATCH * IN_DIM + j * 2 * IN_DIM];                        // x(1)
            xn[2*j + 1] = xp[BATCH * IN_DIM + j * 2 * IN_DIM + IN_DIM];
        }
    }

    for (int s = 0; s < T_STEPS + 2; ++s) {
        u64 ar[3], az[3], ani[3], anh[3];
#pragma unroll
        for (int j = 0; j < 3; j++) { ar[j] = br2; az[j] = bz2; ani[j] = bni2; anh[j] = bnh2; }
#pragma unroll
        for (int k = 0; k < 25; k++) {
            u64 v0 = __shfl_sync(0xffffffffu, sh[0], base + k);      // wraps mod 32
            u64 v1 = __shfl_sync(0xffffffffu, sh[1], base + k);
            u64 v2 = __shfl_sync(0xffffffffu, sh[2], base + k);
            ar[0] = fma2(wr2[k], v0, ar[0]);
            ar[1] = fma2(wr2[k], v1, ar[1]);
            ar[2] = fma2(wr2[k], v2, ar[2]);
            az[0] = fma2(wz2[k], v0, az[0]);
            az[1] = fma2(wz2[k], v1, az[1]);
            az[2] = fma2(wz2[k], v2, az[2]);
            if (k < 15) {
                ani[0] = fma2(wni2[k], v0, ani[0]);
                ani[1] = fma2(wni2[k], v1, ani[1]);
                ani[2] = fma2(wni2[k], v2, ani[2]);
            }
            if (k >= 5) {
                anh[0] = fma2(wnh2[k - 5], v0, anh[0]);
                anh[1] = fma2(wnh2[k - 5], v1, anh[1]);
                anh[2] = fma2(wnh2[k - 5], v2, anh[2]);
            }
        }

        float hn[6];
#pragma unroll
        for (int j = 0; j < 3; j++) {
            float arA, arB, azA, azB, aniA, aniB, anhA, anhB;
            unpack2(ar[j], arA, arB);
            unpack2(az[j], azA, azB);
            unpack2(ani[j], aniA, aniB);
            unpack2(anh[j], anhA, anhB);
            float rA = fsig(arA), rB = fsig(arB);
            float zA = fsig(azA), zB = fsig(azB);
            float nA = ftanh_(fmaf(rA, anhA, aniA));
            float nB = ftanh_(fmaf(rB, anhB, aniB));
            hn[2*j]     = fmaf(zA, h[2*j] - nA, nA);       // (1-z)*n + z*h
            hn[2*j + 1] = fmaf(zB, h[2*j + 1] - nB, nB);
        }

        bool valid = (s >= d) && (s < T_STEPS + d);
        if (valid) {
#pragma unroll
            for (int i = 0; i < 6; i++) h[i] = hn[i];
        }
        if (valid && isOut) {
            size_t o = (size_t)(s - 2) * (BATCH * 2);
#pragma unroll
            for (int j = 0; j < 3; j++) {
                op[o + j * 4]     = hn[2*j];
                op[o + j * 4 + 2] = hn[2*j + 1];
            }
        }

        if (isLoader) {
#pragma unroll
            for (int j = 0; j < 3; j++) sh[j] = pack2(xn[2*j], xn[2*j + 1]);  // x(s+1)
            int t2 = s + 2;
            bool inb = (t2 < T_STEPS);
            size_t xo = (size_t)t2 * (BATCH * IN_DIM);
#pragma unroll
            for (int j = 0; j < 3; j++) {
                xn[2*j]     = inb ? xp[xo + j * 2 * IN_DIM] : 0.f;
                xn[2*j + 1] = inb ? xp[xo + j * 2 * IN_DIM + IN_DIM] : 0.f;
            }
        } else {
#pragma unroll
            for (int j = 0; j < 3; j++) sh[j] = pack2(h[2*j], h[2*j + 1]);
        }
    }
}

extern "C" void kernel_launch(void* const* d_in, const int* in_sizes, int n_in,
                              void* d_out, int out_size)
{
    (void)in_sizes; (void)n_in; (void)out_size;
    const float* x     = (const float*)d_in[0];
    const float* w_ih0 = (const float*)d_in[1];
    const float* w_hh0 = (const float*)d_in[2];
    const float* b_ih0 = (const float*)d_in[3];
    const float* b_hh0 = (const float*)d_in[4];
    const float* w_ih1 = (const float*)d_in[5];
    const float* w_hh1 = (const float*)d_in[6];
    const float* b_ih1 = (const float*)d_in[7];
    const float* b_hh1 = (const float*)d_in[8];
    const float* w_ih2 = (const float*)d_in[9];
    const float* w_hh2 = (const float*)d_in[10];
    const float* b_ih2 = (const float*)d_in[11];
    const float* b_hh2 = (const float*)d_in[12];

    // 6 batches/warp, 5 warps/block: 137 blocks x 160 thr = 685 warps,
    // one block per SM, 30 batches per SM.
    gru3_fused_kernel<<<137, 160>>>(
        x, w_ih0, w_hh0, b_ih0, b_hh0,
        w_ih1, w_hh1, b_ih1, b_hh1,
        w_ih2, w_hh2, b_ih2, b_hh2,
        (float*)d_out);
}